// round 9
// baseline (speedup 1.0000x reference)
#include <cuda_runtime.h>
#include <cuda_bf16.h>
#include <cstdint>

#define D 128
#define MAX_N 100000
#define MAX_E 1600000

// ---------------------------------------------------------------------------
// Scratch (device globals — no allocation allowed)
// ---------------------------------------------------------------------------
__device__ __align__(128) float g_agg[(size_t)MAX_N * D];
__device__ __align__(128) int   g_count[MAX_N];
__device__ __align__(128) int   g_start[MAX_N];
__device__ __align__(128) int   g_cursor[MAX_N];
__device__ __align__(128) long long g_edge[MAX_E];          // packed (w<<32 | col)
// B fragments for mma.sync.m16n8k16 (row.col, bf16):
// [(kstep*16 + ntile)*32 + lane] -> {b0_hi, b1_hi, b0_lo, b1_lo}; ksteps 0-7 Wl, 8-15 Wa.
__device__ __align__(128) uint4 g_Bfrag[16 * 16 * 32];
__device__ int g_total;
__device__ int g_idx_is64;

// ---------------------------------------------------------------------------
// Helpers
// ---------------------------------------------------------------------------
__device__ __forceinline__ uint32_t smem_u32(const void* p) {
    uint32_t a;
    asm("{ .reg .u64 t; cvta.to.shared.u64 t, %1; cvt.u32.u64 %0, t; }" : "=r"(a) : "l"(p));
    return a;
}
__device__ __forceinline__ uint32_t bf16_bits(float f) {
    return (uint32_t)__bfloat16_as_ushort(__float2bfloat16(f));
}
__device__ __forceinline__ float bf16_val(float f) {
    return __bfloat162float(__float2bfloat16(f));
}
__device__ __forceinline__ uint32_t pack_bf16(float lo_elem, float hi_elem) {
    return bf16_bits(lo_elem) | (bf16_bits(hi_elem) << 16);
}
__device__ __forceinline__ void mma_bf16(float* c, const uint32_t* a,
                                         uint32_t b0, uint32_t b1) {
    asm volatile(
        "mma.sync.aligned.m16n8k16.row.col.f32.bf16.bf16.f32 "
        "{%0,%1,%2,%3}, {%4,%5,%6,%7}, {%8,%9}, {%0,%1,%2,%3};"
        : "+f"(c[0]), "+f"(c[1]), "+f"(c[2]), "+f"(c[3])
        : "r"(a[0]), "r"(a[1]), "r"(a[2]), "r"(a[3]), "r"(b0), "r"(b1));
}
__device__ __forceinline__ void ldmatrix_x4(uint32_t* r, uint32_t addr) {
    asm volatile("ldmatrix.sync.aligned.m8n8.x4.shared.b16 {%0,%1,%2,%3}, [%4];"
                 : "=r"(r[0]), "=r"(r[1]), "=r"(r[2]), "=r"(r[3]) : "r"(addr));
}
__device__ __forceinline__ int load_idx(const void* raw, size_t pos) {
    if (g_idx_is64) return (int)((const long long*)raw)[pos];
    return ((const int*)raw)[pos];
}

// ---------------------------------------------------------------------------
// Kernel 1: zero counters + dtype probe (block 0, thread 0).
// ---------------------------------------------------------------------------
__global__ void init_kernel(const int* __restrict__ e32, int n_words, int N) {
    int i = blockIdx.x * blockDim.x + threadIdx.x;
    if (i < N) g_count[i] = 0;
    if (i == 0) {
        g_total = 0;
        int any = 0;
        for (int w = 1; w < 256 && w < n_words; w += 2) any |= e32[w];
        g_idx_is64 = (any == 0) ? 1 : 0;
    }
}

// ---------------------------------------------------------------------------
// Kernel 2 (merged): blocks [0,count_blocks) degree histogram;
//                    blocks [count_blocks, +32) precompute B fragments.
// ---------------------------------------------------------------------------
__global__ void count_prep_kernel(const void* __restrict__ eidx, int E, int N,
                                  int count_blocks,
                                  const float* __restrict__ Wl,
                                  const float* __restrict__ Wa) {
    if (blockIdx.x < (unsigned)count_blocks) {
        int e = blockIdx.x * blockDim.x + threadIdx.x;
        if (e >= E) return;
        int row = load_idx(eidx, e);
        if (row >= 0 && row < N) atomicAdd(&g_count[row], 1);
    } else {
        int id = (blockIdx.x - count_blocks) * blockDim.x + threadIdx.x;
        if (id >= 16 * 16 * 32) return;
        int lane = id & 31;
        int t    = (id >> 5) & 15;   // ntile
        int s    = id >> 9;          // kstep
        int n  = t * 8 + (lane >> 2);
        int k0 = s * 16 + ((lane & 3) << 1);
        float a[4];
#pragma unroll
        for (int j = 0; j < 4; j++) {
            int k = k0 + ((j >> 1) << 3) + (j & 1);
            a[j] = (k < 128) ? Wl[k * 128 + n] : Wa[(k - 128) * 128 + n];
        }
        uint4 v;
        v.x = pack_bf16(a[0], a[1]);
        v.y = pack_bf16(a[2], a[3]);
        v.z = pack_bf16(a[0] - bf16_val(a[0]), a[1] - bf16_val(a[1]));
        v.w = pack_bf16(a[2] - bf16_val(a[2]), a[3] - bf16_val(a[3]));
        g_Bfrag[id] = v;
    }
}

// ---------------------------------------------------------------------------
// Kernel 3: scan-free CSR slot allocation.
// ---------------------------------------------------------------------------
__global__ void alloc_kernel(int N) {
    int n = blockIdx.x * blockDim.x + threadIdx.x;
    if (n >= N) return;
    int c = g_count[n];
    int s = atomicAdd(&g_total, c);
    g_start[n] = s;
    g_cursor[n] = s;
}

// ---------------------------------------------------------------------------
// Kernel 4: bin edges into CSR slots.
// ---------------------------------------------------------------------------
__global__ void fill_kernel(const void* __restrict__ eidx,
                            const float* __restrict__ ew, int E, int N) {
    int e = blockIdx.x * blockDim.x + threadIdx.x;
    if (e >= E) return;
    int row = load_idx(eidx, e);
    int col = load_idx(eidx, (size_t)E + e);
    if (row < 0 || row >= N || col < 0 || col >= N) return;
    float w = ew[e];
    int pos = atomicAdd(&g_cursor[row], 1);
    g_edge[pos] = ((long long)__float_as_int(w) << 32) | (unsigned int)col;
}

// ---------------------------------------------------------------------------
// GEMM body (device function): half-GEMM via mma.sync, 3xBF16 compensated.
//   SELF=true : out[m]  = x[m]   @ Wl + b_lin
//   SELF=false: out[m] += agg[m] @ Wa + deg[m]*b_agg
// BM=128, BN=128, K=128 in 8 steps of k16. 8 warps in 4(M) x 2(N).
// ---------------------------------------------------------------------------
template <bool SELF>
__device__ __forceinline__ void gemm_body(
    const float* __restrict__ src_base,
    const float* __restrict__ bias,
    float* __restrict__ out, int N, int row0,
    uint32_t (*sAhi)[128 * 12], uint32_t (*sAlo)[128 * 12])
{
    const int tid  = threadIdx.x;
    const int wid  = tid >> 5;
    const int lane = tid & 31;
    const int warpM = wid & 3;
    const int warpN = wid >> 2;

    float acc[2][8][4];
#pragma unroll
    for (int m = 0; m < 2; m++)
#pragma unroll
        for (int n = 0; n < 8; n++)
#pragma unroll
            for (int j = 0; j < 4; j++) acc[m][n][j] = 0.f;

    const uint32_t hi_base0 = smem_u32(&sAhi[0][0]);
    const uint32_t lo_base0 = smem_u32(&sAlo[0][0]);

    auto stage = [&](int s, int b) {
        int koff = s * 16;
#pragma unroll
        for (int i = 0; i < 2; i++) {
            int idx = tid + i * 256;
            int r   = idx >> 2;
            int c4  = (idx & 3) << 2;
            int gr  = row0 + r;
            float4 v = make_float4(0.f, 0.f, 0.f, 0.f);
            if (gr < N) v = *(const float4*)(src_base + (size_t)gr * D + koff + c4);
            uint32_t h0 = pack_bf16(v.x, v.y);
            uint32_t h1 = pack_bf16(v.z, v.w);
            uint32_t l0 = pack_bf16(v.x - bf16_val(v.x), v.y - bf16_val(v.y));
            uint32_t l1 = pack_bf16(v.z - bf16_val(v.z), v.w - bf16_val(v.w));
            int o = r * 12 + (c4 >> 1);
            sAhi[b][o] = h0; sAhi[b][o + 1] = h1;
            sAlo[b][o] = l0; sAlo[b][o + 1] = l1;
        }
    };

    stage(0, 0);
    __syncthreads();

#pragma unroll 1
    for (int s = 0; s < 8; s++) {
        int b = s & 1;
        if (s < 7) stage(s + 1, b ^ 1);

        int kstep = SELF ? s : (s + 8);
        uint4 bf[8];
#pragma unroll
        for (int n = 0; n < 8; n++)
            bf[n] = __ldg(&g_Bfrag[((kstep * 16) + warpN * 8 + n) * 32 + lane]);

        uint32_t ahi[2][4], alo[2][4];
        uint32_t lane_off = (uint32_t)(lane & 15) * 48 + ((lane >> 4) << 4);
        uint32_t buf_off  = (uint32_t)b * (128 * 12 * 4);
#pragma unroll
        for (int m = 0; m < 2; m++) {
            uint32_t rowb = (uint32_t)(warpM * 32 + m * 16) * 48;
            ldmatrix_x4(ahi[m], hi_base0 + buf_off + rowb + lane_off);
            ldmatrix_x4(alo[m], lo_base0 + buf_off + rowb + lane_off);
        }

#pragma unroll
        for (int m = 0; m < 2; m++)
#pragma unroll
            for (int n = 0; n < 8; n++) {
                mma_bf16(acc[m][n], ahi[m], bf[n].x, bf[n].y);   // Ahi*Bhi
                mma_bf16(acc[m][n], ahi[m], bf[n].z, bf[n].w);   // Ahi*Blo
                mma_bf16(acc[m][n], alo[m], bf[n].x, bf[n].y);   // Alo*Bhi
            }
        __syncthreads();
    }

    // ---- epilogue ----
    int rbase = row0 + warpM * 32 + (lane >> 2);
#pragma unroll
    for (int m = 0; m < 2; m++) {
        int r_lo = rbase + m * 16;
        int r_hi = r_lo + 8;
        float d_lo = 0.f, d_hi = 0.f;
        if (!SELF) {
            d_lo = (r_lo < N) ? (float)g_count[r_lo] : 0.f;
            d_hi = (r_hi < N) ? (float)g_count[r_hi] : 0.f;
        }
#pragma unroll
        for (int n = 0; n < 8; n++) {
            int c = warpN * 64 + n * 8 + ((lane & 3) << 1);
            float2 bv = *(const float2*)(bias + c);
            if (r_lo < N) {
                float* op = out + (size_t)r_lo * D + c;
                float2 o;
                if (SELF) {
                    o.x = acc[m][n][0] + bv.x;
                    o.y = acc[m][n][1] + bv.y;
                } else {
                    float2 prev = *(const float2*)op;
                    o.x = prev.x + acc[m][n][0] + d_lo * bv.x;
                    o.y = prev.y + acc[m][n][1] + d_lo * bv.y;
                }
                *(float2*)op = o;
            }
            if (r_hi < N) {
                float* op = out + (size_t)r_hi * D + c;
                float2 o;
                if (SELF) {
                    o.x = acc[m][n][2] + bv.x;
                    o.y = acc[m][n][3] + bv.y;
                } else {
                    float2 prev = *(const float2*)op;
                    o.x = prev.x + acc[m][n][2] + d_hi * bv.x;
                    o.y = prev.y + acc[m][n][3] + d_hi * bv.y;
                }
                *(float2*)op = o;
            }
        }
    }
}

// ---------------------------------------------------------------------------
// Kernel 5 (merged): blocks [0,gemm_blocks) -> gemm_self (x@Wl+bl -> out);
//                    blocks [gemm_blocks,..) -> per-node gather-reduce.
// gemm_self is HMMA-bound, aggregate is L2-gather-bound: they overlap.
// ---------------------------------------------------------------------------
__global__ __launch_bounds__(256) void agg_self_kernel(
    const float* __restrict__ x,
    const float* __restrict__ bl,
    float* __restrict__ out, int N, int gemm_blocks)
{
    __shared__ uint32_t sAhi[2][128 * 12];
    __shared__ uint32_t sAlo[2][128 * 12];

    if (blockIdx.x < (unsigned)gemm_blocks) {
        gemm_body<true>(x, bl, out, N, blockIdx.x * 128, sAhi, sAlo);
        return;
    }

    // ---- aggregate role: one warp per node, 8-wide MLP ----
    int node = (blockIdx.x - gemm_blocks) * 8 + (threadIdx.x >> 5);
    int lane = threadIdx.x & 31;
    if (node >= N) return;

    int deg  = g_count[node];
    int base = g_start[node];

    float4 acc = make_float4(0.f, 0.f, 0.f, 0.f);
    for (int e0 = 0; e0 < deg; e0 += 8) {
        long long p[8];
        float4 v[8];
        int m = deg - e0; if (m > 8) m = 8;
#pragma unroll
        for (int j = 0; j < 8; j++)
            if (j < m) p[j] = g_edge[base + e0 + j];
#pragma unroll
        for (int j = 0; j < 8; j++)
            if (j < m) {
                int col = (int)(p[j] & 0xffffffffLL);
                v[j] = *reinterpret_cast<const float4*>(x + (size_t)col * D + lane * 4);
            }
#pragma unroll
        for (int j = 0; j < 8; j++)
            if (j < m) {
                float w = __int_as_float((int)(p[j] >> 32));
                acc.x = fmaf(w, v[j].x, acc.x);
                acc.y = fmaf(w, v[j].y, acc.y);
                acc.z = fmaf(w, v[j].z, acc.z);
                acc.w = fmaf(w, v[j].w, acc.w);
            }
    }
    *reinterpret_cast<float4*>(g_agg + (size_t)node * D + lane * 4) = acc;
}

// ---------------------------------------------------------------------------
// Kernel 6: out += agg@Wa + deg*b_agg
// ---------------------------------------------------------------------------
__global__ __launch_bounds__(256) void gemm_agg_kernel(
    const float* __restrict__ bias, float* __restrict__ out, int N)
{
    __shared__ uint32_t sAhi[2][128 * 12];
    __shared__ uint32_t sAlo[2][128 * 12];
    gemm_body<false>(g_agg, bias, out, N, blockIdx.x * 128, sAhi, sAlo);
}

// ---------------------------------------------------------------------------
extern "C" void kernel_launch(void* const* d_in, const int* in_sizes, int n_in,
                              void* d_out, int out_size) {
    const float* x    = (const float*)d_in[0];
    const void*  eidx = d_in[1];
    const float* ew   = (const float*)d_in[2];
    const float* Wl   = (const float*)d_in[3];
    const float* bl   = (const float*)d_in[4];
    const float* Wa   = (const float*)d_in[5];
    const float* ba   = (const float*)d_in[6];
    float*       out  = (float*)d_out;

    int N = in_sizes[0] / D;   // 100000
    int E = in_sizes[2];       // 1600000

    int count_blocks = (E + 255) / 256;            // 6250
    int prep_blocks  = (16 * 16 * 32 + 255) / 256; // 32
    int gemm_blocks  = (N + 127) / 128;            // 782
    int agg_blocks   = (N + 7) / 8;                // 12500

    init_kernel<<<(N + 255) / 256, 256>>>((const int*)eidx, 2 * E, N);
    count_prep_kernel<<<count_blocks + prep_blocks, 256>>>(eidx, E, N,
                                                           count_blocks, Wl, Wa);
    alloc_kernel<<<(N + 255) / 256, 256>>>(N);
    fill_kernel<<<count_blocks, 256>>>(eidx, ew, E, N);
    agg_self_kernel<<<gemm_blocks + agg_blocks, 256>>>(x, bl, out, N, gemm_blocks);
    gemm_agg_kernel<<<gemm_blocks, 256>>>(ba, out, N);
}

// round 10
// speedup vs baseline: 1.3572x; 1.3572x over previous
#include <cuda_runtime.h>
#include <cuda_bf16.h>
#include <cstdint>

#define D 128
#define MAX_N 100000
#define MAX_E 1600000

// ---------------------------------------------------------------------------
// Scratch (device globals — no allocation allowed)
// ---------------------------------------------------------------------------
__device__ __align__(128) int   g_count[MAX_N];
__device__ __align__(128) int   g_start[MAX_N];
__device__ __align__(128) int   g_cursor[MAX_N];
__device__ __align__(128) long long g_edge[MAX_E];          // packed (w<<32 | col)
// B fragments for mma.sync.m16n8k16 (row.col, bf16):
// [(kstep*16 + ntile)*32 + lane] -> {b0_hi, b1_hi, b0_lo, b1_lo}; ksteps 0-7 Wl, 8-15 Wa.
__device__ __align__(128) uint4 g_Bfrag[16 * 16 * 32];
__device__ int g_total;
__device__ int g_idx_is64;

// ---------------------------------------------------------------------------
// Helpers
// ---------------------------------------------------------------------------
__device__ __forceinline__ uint32_t smem_u32(const void* p) {
    uint32_t a;
    asm("{ .reg .u64 t; cvta.to.shared.u64 t, %1; cvt.u32.u64 %0, t; }" : "=r"(a) : "l"(p));
    return a;
}
__device__ __forceinline__ uint32_t bf16_bits(float f) {
    return (uint32_t)__bfloat16_as_ushort(__float2bfloat16(f));
}
__device__ __forceinline__ float bf16_val(float f) {
    return __bfloat162float(__float2bfloat16(f));
}
__device__ __forceinline__ uint32_t pack_bf16(float lo_elem, float hi_elem) {
    return bf16_bits(lo_elem) | (bf16_bits(hi_elem) << 16);
}
__device__ __forceinline__ void mma_bf16(float* c, const uint32_t* a,
                                         uint32_t b0, uint32_t b1) {
    asm volatile(
        "mma.sync.aligned.m16n8k16.row.col.f32.bf16.bf16.f32 "
        "{%0,%1,%2,%3}, {%4,%5,%6,%7}, {%8,%9}, {%0,%1,%2,%3};"
        : "+f"(c[0]), "+f"(c[1]), "+f"(c[2]), "+f"(c[3])
        : "r"(a[0]), "r"(a[1]), "r"(a[2]), "r"(a[3]), "r"(b0), "r"(b1));
}
__device__ __forceinline__ void ldmatrix_x4(uint32_t* r, uint32_t addr) {
    asm volatile("ldmatrix.sync.aligned.m8n8.x4.shared.b16 {%0,%1,%2,%3}, [%4];"
                 : "=r"(r[0]), "=r"(r[1]), "=r"(r[2]), "=r"(r[3]) : "r"(addr));
}
__device__ __forceinline__ int load_idx(const void* raw, size_t pos) {
    if (g_idx_is64) return (int)((const long long*)raw)[pos];
    return ((const int*)raw)[pos];
}

// ---------------------------------------------------------------------------
// Kernel 1: zero counters + dtype probe.
// ---------------------------------------------------------------------------
__global__ void init_kernel(const int* __restrict__ e32, int n_words, int N) {
    int i = blockIdx.x * blockDim.x + threadIdx.x;
    if (i < N) g_count[i] = 0;
    if (i == 0) {
        g_total = 0;
        int any = 0;
        for (int w = 1; w < 256 && w < n_words; w += 2) any |= e32[w];
        g_idx_is64 = (any == 0) ? 1 : 0;
    }
}

// ---------------------------------------------------------------------------
// Kernel 2 (merged): degree histogram + B-fragment precompute.
// ---------------------------------------------------------------------------
__global__ void count_prep_kernel(const void* __restrict__ eidx, int E, int N,
                                  int count_blocks,
                                  const float* __restrict__ Wl,
                                  const float* __restrict__ Wa) {
    if (blockIdx.x < (unsigned)count_blocks) {
        int e = blockIdx.x * blockDim.x + threadIdx.x;
        if (e >= E) return;
        int row = load_idx(eidx, e);
        if (row >= 0 && row < N) atomicAdd(&g_count[row], 1);
    } else {
        int id = (blockIdx.x - count_blocks) * blockDim.x + threadIdx.x;
        if (id >= 16 * 16 * 32) return;
        int lane = id & 31;
        int t    = (id >> 5) & 15;   // ntile
        int s    = id >> 9;          // kstep
        int n  = t * 8 + (lane >> 2);
        int k0 = s * 16 + ((lane & 3) << 1);
        float a[4];
#pragma unroll
        for (int j = 0; j < 4; j++) {
            int k = k0 + ((j >> 1) << 3) + (j & 1);
            a[j] = (k < 128) ? Wl[k * 128 + n] : Wa[(k - 128) * 128 + n];
        }
        uint4 v;
        v.x = pack_bf16(a[0], a[1]);
        v.y = pack_bf16(a[2], a[3]);
        v.z = pack_bf16(a[0] - bf16_val(a[0]), a[1] - bf16_val(a[1]));
        v.w = pack_bf16(a[2] - bf16_val(a[2]), a[3] - bf16_val(a[3]));
        g_Bfrag[id] = v;
    }
}

// ---------------------------------------------------------------------------
// Kernel 3: scan-free CSR slot allocation.
// ---------------------------------------------------------------------------
__global__ void alloc_kernel(int N) {
    int n = blockIdx.x * blockDim.x + threadIdx.x;
    if (n >= N) return;
    int c = g_count[n];
    int s = atomicAdd(&g_total, c);
    g_start[n] = s;
    g_cursor[n] = s;
}

// ---------------------------------------------------------------------------
// Kernel 4: bin edges into CSR slots.
// ---------------------------------------------------------------------------
__global__ void fill_kernel(const void* __restrict__ eidx,
                            const float* __restrict__ ew, int E, int N) {
    int e = blockIdx.x * blockDim.x + threadIdx.x;
    if (e >= E) return;
    int row = load_idx(eidx, e);
    int col = load_idx(eidx, (size_t)E + e);
    if (row < 0 || row >= N || col < 0 || col >= N) return;
    float w = ew[e];
    int pos = atomicAdd(&g_cursor[row], 1);
    g_edge[pos] = ((long long)__float_as_int(w) << 32) | (unsigned int)col;
}

// ---------------------------------------------------------------------------
// Kernel 5: FUSED aggregate + dual GEMM.
//   Phase 1: each CTA gather-reduces its 64 nodes' weighted neighbor sums
//            into smem (one warp = 8 nodes, 8-wide MLP batching).
//   Phase 2: out[m] = x[m]@Wl + agg[m]@Wa + b_lin + deg[m]*b_agg via
//            mma.sync 3xBF16, K=256 in 16 steps (0-7 from x, 8-15 from smem).
// BM=64, BN=128, 8 warps (2M x 4N, warp tile 32x32). 2 CTAs/SM.
// smem: agg tile f32 [64][144] (pitch 144: %32==16 -> conflict-free LDS.128)
//       + double-buffered hi/lo staging. 48 KB total.
// ---------------------------------------------------------------------------
#define AGG_PITCH 144
__global__ __launch_bounds__(256, 2) void fused_kernel(
    const float* __restrict__ x,
    const float* __restrict__ bl, const float* __restrict__ ba,
    float* __restrict__ out, int N)
{
    extern __shared__ char sm[];
    float*    sAgg = (float*)sm;                       // 64*144*4 = 36864 B
    uint32_t* sAhi = (uint32_t*)(sm + 36864);          // 2*768*4  =  6144 B
    uint32_t* sAlo = (uint32_t*)(sm + 43008);          // 2*768*4  =  6144 B

    const int tid  = threadIdx.x;
    const int wid  = tid >> 5;
    const int lane = tid & 31;
    const int row0 = blockIdx.x * 64;

    // ======================= Phase 1: aggregate =======================
    {
#pragma unroll 1
        for (int i = 0; i < 8; i++) {
            int r    = wid * 8 + i;
            int node = row0 + r;
            int deg = 0, base = 0;
            if (node < N) { deg = g_count[node]; base = g_start[node]; }

            float4 acc = make_float4(0.f, 0.f, 0.f, 0.f);
            for (int e0 = 0; e0 < deg; e0 += 8) {
                long long p[8];
                float4 v[8];
                int m = deg - e0; if (m > 8) m = 8;
#pragma unroll
                for (int j = 0; j < 8; j++)
                    if (j < m) p[j] = g_edge[base + e0 + j];   // broadcast load
#pragma unroll
                for (int j = 0; j < 8; j++)
                    if (j < m) {
                        int col = (int)(p[j] & 0xffffffffLL);
                        v[j] = *reinterpret_cast<const float4*>(
                                   x + (size_t)col * D + lane * 4);
                    }
#pragma unroll
                for (int j = 0; j < 8; j++)
                    if (j < m) {
                        float w = __int_as_float((int)(p[j] >> 32));
                        acc.x = fmaf(w, v[j].x, acc.x);
                        acc.y = fmaf(w, v[j].y, acc.y);
                        acc.z = fmaf(w, v[j].z, acc.z);
                        acc.w = fmaf(w, v[j].w, acc.w);
                    }
            }
            *(float4*)&sAgg[r * AGG_PITCH + lane * 4] = acc;
        }
    }
    __syncthreads();

    // ======================= Phase 2: GEMM =======================
    const int warpM = wid & 1;     // rows warpM*32
    const int warpN = wid >> 1;    // cols warpN*32

    float acc[2][4][4];
#pragma unroll
    for (int m = 0; m < 2; m++)
#pragma unroll
        for (int n = 0; n < 4; n++)
#pragma unroll
            for (int j = 0; j < 4; j++) acc[m][n][j] = 0.f;

    const uint32_t hi_base0 = smem_u32(sAhi);
    const uint32_t lo_base0 = smem_u32(sAlo);

    auto stage = [&](int s, int b) {
        int r  = tid >> 2;          // 0..63
        int c4 = (tid & 3) << 2;    // 0,4,8,12
        float4 v;
        if (s < 8) {
            int gr = row0 + r;
            v = make_float4(0.f, 0.f, 0.f, 0.f);
            if (gr < N) v = *(const float4*)(x + (size_t)gr * D + s * 16 + c4);
        } else {
            v = *(const float4*)&sAgg[r * AGG_PITCH + (s - 8) * 16 + c4];
        }
        uint32_t h0 = pack_bf16(v.x, v.y);
        uint32_t h1 = pack_bf16(v.z, v.w);
        uint32_t l0 = pack_bf16(v.x - bf16_val(v.x), v.y - bf16_val(v.y));
        uint32_t l1 = pack_bf16(v.z - bf16_val(v.z), v.w - bf16_val(v.w));
        int o = b * 768 + r * 12 + (c4 >> 1);
        sAhi[o] = h0; sAhi[o + 1] = h1;
        sAlo[o] = l0; sAlo[o + 1] = l1;
    };

    stage(0, 0);
    __syncthreads();

#pragma unroll 1
    for (int s = 0; s < 16; s++) {
        int b = s & 1;
        if (s < 15) stage(s + 1, b ^ 1);

        uint4 bf[4];
#pragma unroll
        for (int n = 0; n < 4; n++)
            bf[n] = __ldg(&g_Bfrag[((s * 16) + warpN * 4 + n) * 32 + lane]);

        uint32_t ahi[2][4], alo[2][4];
        uint32_t lane_off = (uint32_t)(lane & 15) * 48 + ((lane >> 4) << 4);
        uint32_t buf_off  = (uint32_t)b * (768 * 4);
#pragma unroll
        for (int m = 0; m < 2; m++) {
            uint32_t rowb = (uint32_t)(warpM * 32 + m * 16) * 48;
            ldmatrix_x4(ahi[m], hi_base0 + buf_off + rowb + lane_off);
            ldmatrix_x4(alo[m], lo_base0 + buf_off + rowb + lane_off);
        }

#pragma unroll
        for (int m = 0; m < 2; m++)
#pragma unroll
            for (int n = 0; n < 4; n++) {
                mma_bf16(acc[m][n], ahi[m], bf[n].x, bf[n].y);   // Ahi*Bhi
                mma_bf16(acc[m][n], ahi[m], bf[n].z, bf[n].w);   // Ahi*Blo
                mma_bf16(acc[m][n], alo[m], bf[n].x, bf[n].y);   // Alo*Bhi
            }
        __syncthreads();
    }

    // ---- epilogue: out = acc + b_lin + deg*b_agg ----
    int rbase = row0 + warpM * 32 + (lane >> 2);
#pragma unroll
    for (int m = 0; m < 2; m++) {
        int r_lo = rbase + m * 16;
        int r_hi = r_lo + 8;
        float d_lo = (r_lo < N) ? (float)g_count[r_lo] : 0.f;
        float d_hi = (r_hi < N) ? (float)g_count[r_hi] : 0.f;
#pragma unroll
        for (int n = 0; n < 4; n++) {
            int c = warpN * 32 + n * 8 + ((lane & 3) << 1);
            float2 b1 = *(const float2*)(bl + c);
            float2 b2 = *(const float2*)(ba + c);
            if (r_lo < N) {
                float2 o;
                o.x = acc[m][n][0] + b1.x + d_lo * b2.x;
                o.y = acc[m][n][1] + b1.y + d_lo * b2.y;
                *(float2*)(out + (size_t)r_lo * D + c) = o;
            }
            if (r_hi < N) {
                float2 o;
                o.x = acc[m][n][2] + b1.x + d_hi * b2.x;
                o.y = acc[m][n][3] + b1.y + d_hi * b2.y;
                *(float2*)(out + (size_t)r_hi * D + c) = o;
            }
        }
    }
}

// ---------------------------------------------------------------------------
extern "C" void kernel_launch(void* const* d_in, const int* in_sizes, int n_in,
                              void* d_out, int out_size) {
    const float* x    = (const float*)d_in[0];
    const void*  eidx = d_in[1];
    const float* ew   = (const float*)d_in[2];
    const float* Wl   = (const float*)d_in[3];
    const float* bl   = (const float*)d_in[4];
    const float* Wa   = (const float*)d_in[5];
    const float* ba   = (const float*)d_in[6];
    float*       out  = (float*)d_out;

    int N = in_sizes[0] / D;   // 100000
    int E = in_sizes[2];       // 1600000

    static int attr_set = 0;
    if (!attr_set) {
        cudaFuncSetAttribute(fused_kernel,
                             cudaFuncAttributeMaxDynamicSharedMemorySize, 49152);
        attr_set = 1;
    }

    int count_blocks = (E + 255) / 256;            // 6250
    int prep_blocks  = (16 * 16 * 32 + 255) / 256; // 32
    int fused_blocks = (N + 63) / 64;              // 1563

    init_kernel<<<(N + 255) / 256, 256>>>((const int*)eidx, 2 * E, N);
    count_prep_kernel<<<count_blocks + prep_blocks, 256>>>(eidx, E, N,
                                                           count_blocks, Wl, Wa);
    alloc_kernel<<<(N + 255) / 256, 256>>>(N);
    fill_kernel<<<count_blocks, 256>>>(eidx, ew, E, N);
    fused_kernel<<<fused_blocks, 256, 49152>>>(x, bl, ba, out, N);
}